// round 14
// baseline (speedup 1.0000x reference)
#include <cuda_runtime.h>
#include <math.h>

#define NL   512
#define NH   512
#define ND   512
#define NB   32
#define GCTA 128
#define HC   4
#define PC   12

typedef unsigned long long ull;

// ---------------- device scratch (no allocations allowed) -------------------
__device__ __align__(128) float g_xn[16384 * 512];
__device__ __align__(128) float g_gx[16384 * 1024];
__device__ __align__(128) float g_hs[16384 * 512];
__device__ __align__(128) float g_yb[16384 * 512];
__device__ __align__(128) float g_cU[NH * NB];            // unscaled c, [h][b]
__device__ __align__(128) float g_innovT[NH * NB];        // [h][b]
__device__ __align__(128) float g_kmidT[3 * NH * NB];     // [p][b]
__device__ unsigned g_bar;

// ---------------- grid barrier (release/acquire) -----------------------------
__device__ __forceinline__ void gbar(unsigned target) {
    __syncthreads();
    if (threadIdx.x == 0) {
        asm volatile("red.release.gpu.add.u32 [%0], 1;" :: "l"(&g_bar) : "memory");
        unsigned v;
        do {
            asm volatile("ld.acquire.gpu.u32 %0, [%1];" : "=r"(v) : "l"(&g_bar) : "memory");
        } while (v < target);
    }
    __syncthreads();
}

__global__ void reset_bar_kernel() { g_bar = 0; }

// ---------------- packed f32x2 ops -------------------------------------------
__device__ __forceinline__ void fma2(ull& d, ull a, ull b) {
    asm("fma.rn.f32x2 %0, %1, %2, %0;" : "+l"(d) : "l"(a), "l"(b));
}
__device__ __forceinline__ void add2(ull& d, ull o) {
    asm("add.rn.f32x2 %0, %0, %1;" : "+l"(d) : "l"(o));
}
__device__ __forceinline__ ull pack2(float v) {
    ull r;
    asm("mov.b64 %0, {%1, %1};" : "=l"(r) : "f"(v));
    return r;
}
__device__ __forceinline__ void unpack2(float& lo, float& hi, ull v) {
    asm("mov.b64 {%0, %1}, %2;" : "=f"(lo), "=f"(hi) : "l"(v));
}

// ---------------- RMSNorm ----------------------------------------------------
__global__ void rmsnorm_kernel(const float* __restrict__ x,
                               const float* __restrict__ w,
                               float* __restrict__ o) {
    int row = blockIdx.x;
    int tid = threadIdx.x;                         // 128 threads, 4 floats each
    const float4* xr = (const float4*)(x + (size_t)row * ND);
    float4 v = xr[tid];
    float ss = v.x * v.x + v.y * v.y + v.z * v.z + v.w * v.w;
#pragma unroll
    for (int off = 16; off > 0; off >>= 1)
        ss += __shfl_xor_sync(0xffffffffu, ss, off);
    __shared__ float red[4];
    if ((tid & 31) == 0) red[tid >> 5] = ss;
    __syncthreads();
    float tot = red[0] + red[1] + red[2] + red[3];
    float sc = rsqrtf(tot * (1.0f / ND) + 1e-5f);
    float4 wv = ((const float4*)w)[tid];
    float4 r;
    r.x = v.x * sc * wv.x; r.y = v.y * sc * wv.y;
    r.z = v.z * sc * wv.z; r.w = v.w * sc * wv.w;
    ((float4*)(o + (size_t)row * ND))[tid] = r;
}

// ---------------- SGEMM 128x128x8 (fp32 via f32x2), optional bias ------------
__global__ void __launch_bounds__(256)
sgemm_bias(const float* __restrict__ A, const float* __restrict__ B,
           const float* __restrict__ bias, float* __restrict__ C,
           int M, int N, int K) {
    __shared__ float As[8 * 128];
    __shared__ float Bs[8 * 128];
    int tid = threadIdx.x;
    int row0 = blockIdx.y * 128;
    int col0 = blockIdx.x * 128;
    int arow = tid >> 1, acol4 = (tid & 1) * 4;
    int bkk = tid >> 5, bcol = (tid & 31) * 4;
    int ty = tid >> 4, tx = tid & 15;
    ull acc[8][4];
#pragma unroll
    for (int i = 0; i < 8; i++)
#pragma unroll
        for (int j = 0; j < 4; j++) acc[i][j] = 0;

    for (int k0 = 0; k0 < K; k0 += 8) {
        float4 av = *(const float4*)(A + (size_t)(row0 + arow) * K + k0 + acol4);
        As[(acol4 + 0) * 128 + arow] = av.x;
        As[(acol4 + 1) * 128 + arow] = av.y;
        As[(acol4 + 2) * 128 + arow] = av.z;
        As[(acol4 + 3) * 128 + arow] = av.w;
        *(float4*)(Bs + bkk * 128 + bcol) =
            *(const float4*)(B + (size_t)(k0 + bkk) * N + col0 + bcol);
        __syncthreads();
#pragma unroll
        for (int kk = 0; kk < 8; kk++) {
            float ra[8];
            *(float4*)(ra)     = *(const float4*)(As + kk * 128 + ty * 8);
            *(float4*)(ra + 4) = *(const float4*)(As + kk * 128 + ty * 8 + 4);
            const ulonglong2* pb = (const ulonglong2*)(Bs + kk * 128 + tx * 8);
            ulonglong2 b01 = pb[0];
            ulonglong2 b23 = pb[1];
#pragma unroll
            for (int i = 0; i < 8; i++) {
                ull ap = pack2(ra[i]);
                fma2(acc[i][0], ap, b01.x);
                fma2(acc[i][1], ap, b01.y);
                fma2(acc[i][2], ap, b23.x);
                fma2(acc[i][3], ap, b23.y);
            }
        }
        __syncthreads();
    }
#pragma unroll
    for (int i = 0; i < 8; i++) {
        int r = row0 + ty * 8 + i;
        float f[8];
#pragma unroll
        for (int jp = 0; jp < 4; jp++) unpack2(f[2 * jp], f[2 * jp + 1], acc[i][jp]);
#pragma unroll
        for (int j4 = 0; j4 < 8; j4 += 4) {
            int c = col0 + tx * 8 + j4;
            float4 v;
            v.x = f[j4];     v.y = f[j4 + 1];
            v.z = f[j4 + 2]; v.w = f[j4 + 3];
            if (bias) {
                v.x += bias[c];     v.y += bias[c + 1];
                v.z += bias[c + 2]; v.w += bias[c + 3];
            }
            *(float4*)(C + (size_t)r * N + c) = v;
        }
    }
}

// ---------------- persistent scan kernel (1024 threads) ----------------------
// smem layout (floats):
//  s_wzm  [0,      8192)  : W_hh z/m cols, dup pairs [c8][1024]
//  s_w1   [8192,  20480)  : k_W1 cols, dup pairs [c12][1024]
//  s_w2   [20480, 32768)  : k_W2 cols, dup pairs [c4][3072]
//  s_act  [32768, 49152)  : c / innov staging [k512][b32]
//  s_part [49152, 55296)  : split-k partials, ull
//  s_red  [55296, 56320)  : sumsq partials [w32][g8][4]
//  s_zm   [56320, 56576)
//  s_inn  [56576, 56704)
//  s_M    [56704, 56832)
//  s_cold [56832, 56960)
//  s_A    [56960, 57088)
//  s_scale[57088, 57120)
//  s_b    [57120, 57152)
#define SCAN_SMEM_FLOATS 57152

__global__ void __launch_bounds__(1024, 1)
scan_kernel(const float* __restrict__ gx,
            const float* __restrict__ Whh,       // [512][1024] this layer
            const float* __restrict__ b_hh,
            const float* __restrict__ log_lambda,
            const float* __restrict__ kW1,       // [512][1536]
            const float* __restrict__ kb1,
            const float* __restrict__ kW2,       // [1536][512]
            const float* __restrict__ kb2) {
    extern __shared__ float sm[];
    float* s_wzm   = sm;
    float* s_w1    = sm + 8192;
    float* s_w2    = sm + 20480;
    float* s_act   = sm + 32768;
    ull*   s_part  = (ull*)(sm + 49152);
    float* s_partf = sm + 49152;
    float* s_red   = sm + 55296;
    float* s_zm    = sm + 56320;
    float* s_inn   = sm + 56576;
    float* s_M     = sm + 56704;
    float* s_cold  = sm + 56832;
    float* s_A     = sm + 56960;
    float* s_scale = sm + 57088;
    float* s_b     = sm + 57120;

    const int tid  = threadIdx.x;
    const int cta  = blockIdx.x;
    const int w32  = tid >> 5;          // 0..31
    const int w    = w32 & 15;          // k-slice warp for zm/ph1
    const int cg   = tid >> 9;          // c-group (0/1) for zm/ph1
    const int lane = tid & 31;
    const int half = lane >> 4;
    const int bp   = lane & 15;
    const int ks   = w * 32 + half * 16;        // zm/ph1: 16 k's per thread
    const int ks2  = w32 * 48 + half * 24;      // ph2: 24 k's per thread
    const int j0   = cta * HC;
    const int p0   = cta * PC;

    // ---- one-time: gather owned weight columns into smem, duplicated -------
    for (int i = tid; i < 8 * 512; i += 1024) {
        int c = i >> 9, k = i & 511;
        int col = (c < 4) ? (j0 + c) : (512 + j0 + c - 4);
        float wv = Whh[(size_t)k * 1024 + col];
        *(float2*)(s_wzm + c * 1024 + 2 * k) = make_float2(wv, wv);
    }
    for (int i = tid; i < 12 * 512; i += 1024) {
        int c = i >> 9, k = i & 511;
        float wv = kW1[(size_t)k * 1536 + p0 + c];
        *(float2*)(s_w1 + c * 1024 + 2 * k) = make_float2(wv, wv);
    }
    for (int i = tid; i < 4 * 1536; i += 1024) {
        int c = i / 1536, k = i % 1536;
        float wv = kW2[(size_t)k * 512 + j0 + c];
        *(float2*)(s_w2 + c * 3072 + 2 * k) = make_float2(wv, wv);
    }
    if (tid < 8)  s_b[tid] = (tid < 4) ? b_hh[j0 + tid] : b_hh[512 + j0 + tid - 4];
    if (tid < 12) s_b[8 + tid] = kb1[p0 + tid];
    if (tid < 4) {
        s_b[20 + tid] = kb2[j0 + tid];
        s_b[24 + tid] = 1.0f - expf(log_lambda[j0 + tid]);
    }
    if (tid < 128) {
        s_A[tid] = 0.0f;
        int c = tid >> 5, b = tid & 31;
        __stcg(&g_cU[(j0 + c) * 32 + b], 0.0f);
    }
    unsigned nb = 1;
    gbar(nb * GCTA); nb++;

    for (int t = 0; t <= NL; t++) {
        // ==== Phase Z: stage unscaled c + per-batch sumsq (deterministic) ===
        float ss0 = 0.f, ss1 = 0.f, ss2 = 0.f, ss3 = 0.f;
#pragma unroll
        for (int r = 0; r < 4; r++) {
            int i4 = tid + 1024 * r;
            float4 v = __ldcg(((const float4*)g_cU) + i4);
            ((float4*)s_act)[i4] = v;
            ss0 += v.x * v.x; ss1 += v.y * v.y;
            ss2 += v.z * v.z; ss3 += v.w * v.w;
        }
#pragma unroll
        for (int off = 16; off >= 8; off >>= 1) {
            ss0 += __shfl_xor_sync(0xffffffffu, ss0, off);
            ss1 += __shfl_xor_sync(0xffffffffu, ss1, off);
            ss2 += __shfl_xor_sync(0xffffffffu, ss2, off);
            ss3 += __shfl_xor_sync(0xffffffffu, ss3, off);
        }
        if (lane < 8)
            ((float4*)s_red)[w32 * 8 + lane] = make_float4(ss0, ss1, ss2, ss3);
        __syncthreads();
        if (tid < 32) {
            int g = tid >> 2, slot = tid & 3;
            float sum = 0.f;
#pragma unroll
            for (int ww = 0; ww < 32; ww++) sum += s_red[ww * 32 + g * 4 + slot];
            s_scale[tid] = fminf(1.0f, 10.0f * rsqrtf(sum + 1e-6f));
        }
        __syncthreads();
        if (t > 0 && tid < 128) {           // hs[t-1] = scaled c (own cols)
            int c = tid >> 5, b = tid & 31;
            g_hs[((size_t)b * NL + (t - 1)) * NH + j0 + c] =
                s_act[(j0 + c) * 32 + b] * s_scale[b];
        }
        if (t == NL) break;

        // gx prefetch (first 256 threads: col group tid>>5, batch tid&31)
        float gxv = 0.f;
        if (tid < 256) {
            int cgx = tid >> 5;
            int colg = (cgx < 4) ? (j0 + cgx) : (512 + j0 + (cgx - 4));
            gxv = __ldg(&gx[((size_t)(tid & 31) * NL + t) * 1024 + colg]);
        }

        // ==== zm split-k (f32x2): 16 k's, 4 c's (cg half) per thread ========
        {
            ull acc[4] = {0, 0, 0, 0};
            const int cb = cg * 4;
#pragma unroll
            for (int kq = 0; kq < 4; kq++) {
                int k = ks + 4 * kq;
                ull a0 = *(const ull*)(s_act + (k + 0) * 32 + 2 * bp);
                ull a1 = *(const ull*)(s_act + (k + 1) * 32 + 2 * bp);
                ull a2 = *(const ull*)(s_act + (k + 2) * 32 + 2 * bp);
                ull a3 = *(const ull*)(s_act + (k + 3) * 32 + 2 * bp);
#pragma unroll
                for (int c = 0; c < 4; c++) {
                    const float* wp = s_wzm + (cb + c) * 1024 + 2 * k;
                    ulonglong2 w01 = *(const ulonglong2*)(wp);
                    ulonglong2 w23 = *(const ulonglong2*)(wp + 4);
                    fma2(acc[c], a0, w01.x); fma2(acc[c], a1, w01.y);
                    fma2(acc[c], a2, w23.x); fma2(acc[c], a3, w23.y);
                }
            }
#pragma unroll
            for (int c = 0; c < 4; c++) {
                ull o = __shfl_xor_sync(0xffffffffu, acc[c], 16);
                add2(acc[c], o);
            }
            if (lane < 16) {
#pragma unroll
                for (int c = 0; c < 4; c++)
                    s_part[(w * 8 + cb + c) * 16 + bp] = acc[c];
            }
        }
        __syncthreads();
        if (tid < 256) {   // reduce 16 warp-slices: z/m = raw*scale + gx + b
            int c = tid >> 5, b = tid & 31;
            float raw = 0.f;
#pragma unroll
            for (int s = 0; s < 16; s++)
                raw += s_partf[(((s * 8 + c) * 16 + (b >> 1)) << 1) | (b & 1)];
            s_zm[c * 32 + b] = raw * s_scale[b] + gxv + s_b[c];
        }
        __syncthreads();
        if (tid < 128) {
            float z = s_zm[tid];
            float m = s_zm[128 + tid];
            float Mv = tanhf(m);
            int c = tid >> 5, b = tid & 31;
            float cS = s_act[(j0 + c) * 32 + b] * s_scale[b];
            float innov = z - s_A[tid] * cS - Mv;
            s_inn[tid] = innov; s_M[tid] = Mv; s_cold[tid] = cS;
            __stcg(&g_innovT[(j0 + c) * 32 + b], innov);
        }
        gbar(nb * GCTA); nb++;

        // ==== Phase 1: stage innov, kmid = gelu(innov @ kW1 + kb1) ==========
#pragma unroll
        for (int r = 0; r < 4; r++) {
            int i4 = tid + 1024 * r;
            ((float4*)s_act)[i4] = __ldcg(((const float4*)g_innovT) + i4);
        }
        __syncthreads();
        {
            ull acc1[6];
#pragma unroll
            for (int c = 0; c < 6; c++) acc1[c] = 0;
            const int cb = cg * 6;
#pragma unroll
            for (int kq = 0; kq < 4; kq++) {
                int k = ks + 4 * kq;
                ull a0 = *(const ull*)(s_act + (k + 0) * 32 + 2 * bp);
                ull a1 = *(const ull*)(s_act + (k + 1) * 32 + 2 * bp);
                ull a2 = *(const ull*)(s_act + (k + 2) * 32 + 2 * bp);
                ull a3 = *(const ull*)(s_act + (k + 3) * 32 + 2 * bp);
#pragma unroll
                for (int c = 0; c < 6; c++) {
                    const float* wp = s_w1 + (cb + c) * 1024 + 2 * k;
                    ulonglong2 w01 = *(const ulonglong2*)(wp);
                    ulonglong2 w23 = *(const ulonglong2*)(wp + 4);
                    fma2(acc1[c], a0, w01.x); fma2(acc1[c], a1, w01.y);
                    fma2(acc1[c], a2, w23.x); fma2(acc1[c], a3, w23.y);
                }
            }
#pragma unroll
            for (int c = 0; c < 6; c++) {
                ull o = __shfl_xor_sync(0xffffffffu, acc1[c], 16);
                add2(acc1[c], o);
            }
            if (lane < 16) {
#pragma unroll
                for (int c = 0; c < 6; c++)
                    s_part[(w * 12 + cb + c) * 16 + bp] = acc1[c];
            }
        }
        __syncthreads();
        if (tid < 384) {
            int c = tid >> 5, b = tid & 31;
            float sum = 0.f;
#pragma unroll
            for (int s = 0; s < 16; s++)
                sum += s_partf[(((s * 12 + c) * 16 + (b >> 1)) << 1) | (b & 1)];
            sum += s_b[8 + c];
            float ge = 0.5f * sum * (1.0f + erff(sum * 0.70710678118654752f));
            __stcg(&g_kmidT[(p0 + c) * 32 + b], ge);
        }
        gbar(nb * GCTA); nb++;

        // ==== Phase 2: K = tanh(kmid @ kW2 + kb2)*0.5; 32 k-slices of 48 ====
        {
            ull acc2[4] = {0, 0, 0, 0};
            const ull* kp = (const ull*)g_kmidT;
#pragma unroll
            for (int kq = 0; kq < 6; kq++) {
                int k = ks2 + 4 * kq;
                ull a0 = __ldcg(kp + (k + 0) * 16 + bp);
                ull a1 = __ldcg(kp + (k + 1) * 16 + bp);
                ull a2 = __ldcg(kp + (k + 2) * 16 + bp);
                ull a3 = __ldcg(kp + (k + 3) * 16 + bp);
#pragma unroll
                for (int c = 0; c < 4; c++) {
                    const float* wp = s_w2 + c * 3072 + 2 * k;
                    ulonglong2 w01 = *(const ulonglong2*)(wp);
                    ulonglong2 w23 = *(const ulonglong2*)(wp + 4);
                    fma2(acc2[c], a0, w01.x); fma2(acc2[c], a1, w01.y);
                    fma2(acc2[c], a2, w23.x); fma2(acc2[c], a3, w23.y);
                }
            }
#pragma unroll
            for (int c = 0; c < 4; c++) {
                ull o = __shfl_xor_sync(0xffffffffu, acc2[c], 16);
                add2(acc2[c], o);
            }
            if (lane < 16) {
#pragma unroll
                for (int c = 0; c < 4; c++)
                    s_part[(w32 * 4 + c) * 16 + bp] = acc2[c];
            }
        }
        __syncthreads();
        if (tid < 128) {
            int c = tid >> 5, b = tid & 31;
            float sum = 0.f;
#pragma unroll
            for (int s = 0; s < 32; s++)
                sum += s_partf[(((s * 4 + c) * 16 + (b >> 1)) << 1) | (b & 1)];
            float K  = tanhf(sum + s_b[20 + c]) * 0.5f;
            float An = s_b[24 + c] * (1.0f - K * K);
            float cn = An * s_cold[tid] + K * s_inn[tid] + s_M[tid];
            s_A[tid] = An;
            __stcg(&g_cU[(j0 + c) * 32 + b], cn);
        }
        gbar(nb * GCTA); nb++;
    }
}

// ---------------- launch orchestration ---------------------------------------
extern "C" void kernel_launch(void* const* d_in, const int* in_sizes, int n_in,
                              void* d_out, int out_size) {
    const float* x          = (const float*)d_in[0];
    const float* norm_w     = (const float*)d_in[1];
    const float* W_ih       = (const float*)d_in[2];
    const float* b_ih       = (const float*)d_in[3];
    const float* W_hh       = (const float*)d_in[4];
    const float* b_hh       = (const float*)d_in[5];
    const float* log_lambda = (const float*)d_in[6];
    const float* k_W1       = (const float*)d_in[7];
    const float* k_b1       = (const float*)d_in[8];
    const float* k_W2       = (const float*)d_in[9];
    const float* k_b2       = (const float*)d_in[10];
    const float* Wo         = (const float*)d_in[11];
    float* out = (float*)d_out;

    float *p_xn, *p_gx, *p_hs, *p_yb;
    cudaGetSymbolAddress((void**)&p_xn, g_xn);
    cudaGetSymbolAddress((void**)&p_gx, g_gx);
    cudaGetSymbolAddress((void**)&p_hs, g_hs);
    cudaGetSymbolAddress((void**)&p_yb, g_yb);

    cudaFuncSetAttribute(scan_kernel,
                         cudaFuncAttributeMaxDynamicSharedMemorySize,
                         SCAN_SMEM_FLOATS * 4);

    for (int l = 0; l < 2; l++) {
        const float* xin = (l == 0) ? x : p_yb;
        rmsnorm_kernel<<<16384, 128>>>(xin, norm_w, p_xn);
        sgemm_bias<<<dim3(8, 128), 256>>>(p_xn, W_ih + (size_t)l * 512 * 1024,
                                          b_ih + l * 1024, p_gx,
                                          16384, 1024, 512);
        reset_bar_kernel<<<1, 1>>>();
        scan_kernel<<<GCTA, 1024, SCAN_SMEM_FLOATS * 4>>>(
            p_gx,
            W_hh + (size_t)l * 512 * 1024, b_hh + l * 1024,
            log_lambda + l * 512,
            k_W1 + (size_t)l * 512 * 1536, k_b1 + l * 1536,
            k_W2 + (size_t)l * 1536 * 512, k_b2 + l * 512);
        sgemm_bias<<<dim3(4, 128), 256>>>(p_hs, Wo + (size_t)l * 512 * 512,
                                          nullptr, (l == 0) ? p_yb : out,
                                          16384, 512, 512);
    }
}

// round 16
// speedup vs baseline: 1.1901x; 1.1901x over previous
#include <cuda_runtime.h>
#include <math.h>

#define NL   512
#define NH   512
#define ND   512
#define NB   32
#define GCTA 128
#define HC   4
#define PC   12

typedef unsigned long long ull;

// ---------------- device scratch (no allocations allowed) -------------------
__device__ __align__(128) float g_xn[16384 * 512];
__device__ __align__(128) float g_gx[16384 * 1024];
__device__ __align__(128) float g_hs[16384 * 512];
__device__ __align__(128) float g_yb[16384 * 512];
__device__ __align__(128) float g_cU[NH * NB];            // unscaled c, [h][b]
__device__ __align__(128) float g_innovT[NH * NB];        // [h][b]
__device__ __align__(128) float g_kmidT[3 * NH * NB];     // [p][b]
__device__ unsigned g_bar;

// ---------------- grid barrier (release/acquire) -----------------------------
__device__ __forceinline__ void gbar(unsigned target) {
    __syncthreads();
    if (threadIdx.x == 0) {
        asm volatile("red.release.gpu.add.u32 [%0], 1;" :: "l"(&g_bar) : "memory");
        unsigned v;
        do {
            asm volatile("ld.acquire.gpu.u32 %0, [%1];" : "=r"(v) : "l"(&g_bar) : "memory");
        } while (v < target);
    }
    __syncthreads();
}

__global__ void reset_bar_kernel() { g_bar = 0; }

// ---------------- packed f32x2 ops -------------------------------------------
__device__ __forceinline__ void fma2(ull& d, ull a, ull b) {
    asm("fma.rn.f32x2 %0, %1, %2, %0;" : "+l"(d) : "l"(a), "l"(b));
}
__device__ __forceinline__ void add2(ull& d, ull o) {
    asm("add.rn.f32x2 %0, %0, %1;" : "+l"(d) : "l"(o));
}
__device__ __forceinline__ ull pack2(float v) {
    ull r;
    asm("mov.b64 %0, {%1, %1};" : "=l"(r) : "f"(v));
    return r;
}
__device__ __forceinline__ void unpack2(float& lo, float& hi, ull v) {
    asm("mov.b64 {%0, %1}, %2;" : "=f"(lo), "=f"(hi) : "l"(v));
}

// ---------------- RMSNorm ----------------------------------------------------
__global__ void rmsnorm_kernel(const float* __restrict__ x,
                               const float* __restrict__ w,
                               float* __restrict__ o) {
    int row = blockIdx.x;
    int tid = threadIdx.x;                         // 128 threads, 4 floats each
    const float4* xr = (const float4*)(x + (size_t)row * ND);
    float4 v = xr[tid];
    float ss = v.x * v.x + v.y * v.y + v.z * v.z + v.w * v.w;
#pragma unroll
    for (int off = 16; off > 0; off >>= 1)
        ss += __shfl_xor_sync(0xffffffffu, ss, off);
    __shared__ float red[4];
    if ((tid & 31) == 0) red[tid >> 5] = ss;
    __syncthreads();
    float tot = red[0] + red[1] + red[2] + red[3];
    float sc = rsqrtf(tot * (1.0f / ND) + 1e-5f);
    float4 wv = ((const float4*)w)[tid];
    float4 r;
    r.x = v.x * sc * wv.x; r.y = v.y * sc * wv.y;
    r.z = v.z * sc * wv.z; r.w = v.w * sc * wv.w;
    ((float4*)(o + (size_t)row * ND))[tid] = r;
}

// ---------------- SGEMM 128x128x8 (fp32 via f32x2), optional bias ------------
__global__ void __launch_bounds__(256)
sgemm_bias(const float* __restrict__ A, const float* __restrict__ B,
           const float* __restrict__ bias, float* __restrict__ C,
           int M, int N, int K) {
    __shared__ float As[8 * 128];
    __shared__ float Bs[8 * 128];
    int tid = threadIdx.x;
    int row0 = blockIdx.y * 128;
    int col0 = blockIdx.x * 128;
    int arow = tid >> 1, acol4 = (tid & 1) * 4;
    int bkk = tid >> 5, bcol = (tid & 31) * 4;
    int ty = tid >> 4, tx = tid & 15;
    ull acc[8][4];
#pragma unroll
    for (int i = 0; i < 8; i++)
#pragma unroll
        for (int j = 0; j < 4; j++) acc[i][j] = 0;

    for (int k0 = 0; k0 < K; k0 += 8) {
        float4 av = *(const float4*)(A + (size_t)(row0 + arow) * K + k0 + acol4);
        As[(acol4 + 0) * 128 + arow] = av.x;
        As[(acol4 + 1) * 128 + arow] = av.y;
        As[(acol4 + 2) * 128 + arow] = av.z;
        As[(acol4 + 3) * 128 + arow] = av.w;
        *(float4*)(Bs + bkk * 128 + bcol) =
            *(const float4*)(B + (size_t)(k0 + bkk) * N + col0 + bcol);
        __syncthreads();
#pragma unroll
        for (int kk = 0; kk < 8; kk++) {
            float ra[8];
            *(float4*)(ra)     = *(const float4*)(As + kk * 128 + ty * 8);
            *(float4*)(ra + 4) = *(const float4*)(As + kk * 128 + ty * 8 + 4);
            const ulonglong2* pb = (const ulonglong2*)(Bs + kk * 128 + tx * 8);
            ulonglong2 b01 = pb[0];
            ulonglong2 b23 = pb[1];
#pragma unroll
            for (int i = 0; i < 8; i++) {
                ull ap = pack2(ra[i]);
                fma2(acc[i][0], ap, b01.x);
                fma2(acc[i][1], ap, b01.y);
                fma2(acc[i][2], ap, b23.x);
                fma2(acc[i][3], ap, b23.y);
            }
        }
        __syncthreads();
    }
#pragma unroll
    for (int i = 0; i < 8; i++) {
        int r = row0 + ty * 8 + i;
        float f[8];
#pragma unroll
        for (int jp = 0; jp < 4; jp++) unpack2(f[2 * jp], f[2 * jp + 1], acc[i][jp]);
#pragma unroll
        for (int j4 = 0; j4 < 8; j4 += 4) {
            int c = col0 + tx * 8 + j4;
            float4 v;
            v.x = f[j4];     v.y = f[j4 + 1];
            v.z = f[j4 + 2]; v.w = f[j4 + 3];
            if (bias) {
                v.x += bias[c];     v.y += bias[c + 1];
                v.z += bias[c + 2]; v.w += bias[c + 3];
            }
            *(float4*)(C + (size_t)r * N + c) = v;
        }
    }
}

// ---------------- persistent scan kernel (512 threads) -----------------------
// smem layout (floats):
//  s_wzm  [0,      8192)  : W_hh z/m cols, dup pairs [c8][1024]
//  s_w1   [8192,  20480)  : k_W1 cols, dup pairs [c12][1024]
//  s_w2   [20480, 32768)  : k_W2 cols, dup pairs [c4][3072]
//  s_part [32768, 38912)  : split-k partials, ull (max 16*12*16)
//  s_inn  [38912, 39040)
//  s_M    [39040, 39168)
//  s_cold [39168, 39296)
//  s_A    [39296, 39424)
//  s_b    [39424, 39456)
#define SCAN_SMEM_FLOATS 39456

__global__ void __launch_bounds__(512, 1)
scan_kernel(const float* __restrict__ gx,
            const float* __restrict__ Whh,       // [512][1024] this layer
            const float* __restrict__ b_hh,
            const float* __restrict__ log_lambda,
            const float* __restrict__ kW1,       // [512][1536]
            const float* __restrict__ kb1,
            const float* __restrict__ kW2,       // [1536][512]
            const float* __restrict__ kb2) {
    extern __shared__ float sm[];
    float* s_wzm   = sm;
    float* s_w1    = sm + 8192;
    float* s_w2    = sm + 20480;
    ull*   s_part  = (ull*)(sm + 32768);
    float* s_partf = sm + 32768;
    float* s_inn   = sm + 38912;
    float* s_M     = sm + 39040;
    float* s_cold  = sm + 39168;
    float* s_A     = sm + 39296;
    float* s_b     = sm + 39424;

    const int tid  = threadIdx.x;
    const int cta  = blockIdx.x;
    const int w    = tid >> 5;          // 0..15
    const int lane = tid & 31;
    const int half = lane >> 4;
    const int bp   = lane & 15;
    const int ks   = w * 32 + half * 16;        // zm/ph1: 16 k's per thread
    const int ks2  = w * 96 + half * 48;        // ph2: 48 k's per thread (12x4)
    const int j0   = cta * HC;
    const int p0   = cta * PC;
    const int cI   = tid >> 5;                  // innov-phase col (tid<128)
    const int bI   = tid & 31;                  // innov-phase batch

    // ---- one-time: gather owned weight columns into smem, duplicated -------
    for (int i = tid; i < 8 * 512; i += 512) {
        int c = i >> 9, k = i & 511;
        int col = (c < 4) ? (j0 + c) : (512 + j0 + c - 4);
        float wv = Whh[(size_t)k * 1024 + col];
        *(float2*)(s_wzm + c * 1024 + 2 * k) = make_float2(wv, wv);
    }
    for (int i = tid; i < 12 * 512; i += 512) {
        int c = i >> 9, k = i & 511;
        float wv = kW1[(size_t)k * 1536 + p0 + c];
        *(float2*)(s_w1 + c * 1024 + 2 * k) = make_float2(wv, wv);
    }
    for (int i = tid; i < 4 * 1536; i += 512) {
        int c = i / 1536, k = i % 1536;
        float wv = kW2[(size_t)k * 512 + j0 + c];
        *(float2*)(s_w2 + c * 3072 + 2 * k) = make_float2(wv, wv);
    }
    if (tid < 8)  s_b[tid] = (tid < 4) ? b_hh[j0 + tid] : b_hh[512 + j0 + tid - 4];
    if (tid < 12) s_b[8 + tid] = kb1[p0 + tid];
    if (tid < 4) {
        s_b[20 + tid] = kb2[j0 + tid];
        s_b[24 + tid] = 1.0f - expf(log_lambda[j0 + tid]);
    }
    if (tid < 128) {
        s_A[tid] = 0.0f;
        __stcg(&g_cU[(j0 + cI) * 32 + bI], 0.0f);
    }
    unsigned nb = 1;
    gbar(nb * GCTA); nb++;

    for (int t = 0; t < NL; t++) {
        // ---- prefetch own c + both gx gates (off critical path) ------------
        float cOwn = 0.f, gxz = 0.f, gxm = 0.f;
        if (tid < 128) {
            cOwn = __ldcg(&g_cU[(j0 + cI) * 32 + bI]);
            const float* gr = gx + ((size_t)bI * NL + t) * 1024;
            gxz = __ldg(gr + j0 + cI);
            gxm = __ldg(gr + 512 + j0 + cI);
        }

        // ==== zm split-k (f32x2) over L2 c, fused sumsq ======================
        {
            ull acc[8] = {0, 0, 0, 0, 0, 0, 0, 0};
            ull ss2 = 0;
            const ull* cp = (const ull*)g_cU;
#pragma unroll
            for (int kq = 0; kq < 4; kq++) {
                int k = ks + 4 * kq;
                ull a0 = __ldcg(cp + (k + 0) * 16 + bp);
                ull a1 = __ldcg(cp + (k + 1) * 16 + bp);
                ull a2 = __ldcg(cp + (k + 2) * 16 + bp);
                ull a3 = __ldcg(cp + (k + 3) * 16 + bp);
                fma2(ss2, a0, a0); fma2(ss2, a1, a1);
                fma2(ss2, a2, a2); fma2(ss2, a3, a3);
#pragma unroll
                for (int c = 0; c < 8; c++) {
                    const float* wp = s_wzm + c * 1024 + 2 * k;
                    ulonglong2 w01 = *(const ulonglong2*)(wp);
                    ulonglong2 w23 = *(const ulonglong2*)(wp + 4);
                    fma2(acc[c], a0, w01.x); fma2(acc[c], a1, w01.y);
                    fma2(acc[c], a2, w23.x); fma2(acc[c], a3, w23.y);
                }
            }
#pragma unroll
            for (int c = 0; c < 8; c++) {
                ull o = __shfl_xor_sync(0xffffffffu, acc[c], 16);
                add2(acc[c], o);
            }
            {
                ull o = __shfl_xor_sync(0xffffffffu, ss2, 16);
                add2(ss2, o);
            }
            if (lane < 16) {
#pragma unroll
                for (int c = 0; c < 8; c++)
                    s_part[(w * 9 + c) * 16 + bp] = acc[c];
                s_part[(w * 9 + 8) * 16 + bp] = ss2;
            }
        }
        __syncthreads();
        // ==== fused reduce + scale + innov + hs (128 threads) ===============
        if (tid < 128) {
            float ssum = 0.f, zr = 0.f, mr = 0.f;
#pragma unroll
            for (int s = 0; s < 16; s++) {
                int rb = s * 9;
                ssum += s_partf[(((rb + 8) * 16 + (bI >> 1)) << 1) | (bI & 1)];
                zr   += s_partf[(((rb + cI) * 16 + (bI >> 1)) << 1) | (bI & 1)];
                mr   += s_partf[(((rb + 4 + cI) * 16 + (bI >> 1)) << 1) | (bI & 1)];
            }
            float scale = fminf(1.0f, 10.0f * rsqrtf(ssum + 1e-6f));
            float z = zr * scale + gxz + s_b[cI];
            float m = mr * scale + gxm + s_b[4 + cI];
            float Mv = tanhf(m);
            float cS = cOwn * scale;
            float innov = z - s_A[tid] * cS - Mv;
            s_inn[tid] = innov; s_M[tid] = Mv; s_cold[tid] = cS;
            __stcg(&g_innovT[(j0 + cI) * 32 + bI], innov);
            if (t > 0)
                g_hs[((size_t)bI * NL + (t - 1)) * NH + j0 + cI] = cS;
        }
        gbar(nb * GCTA); nb++;

        // ==== Phase 1: kmid = gelu(innov @ kW1 + kb1), direct ldcg ==========
        {
            ull acc1[12];
#pragma unroll
            for (int c = 0; c < 12; c++) acc1[c] = 0;
            const ull* ip = (const ull*)g_innovT;
#pragma unroll
            for (int kq = 0; kq < 4; kq++) {
                int k = ks + 4 * kq;
                ull a0 = __ldcg(ip + (k + 0) * 16 + bp);
                ull a1 = __ldcg(ip + (k + 1) * 16 + bp);
                ull a2 = __ldcg(ip + (k + 2) * 16 + bp);
                ull a3 = __ldcg(ip + (k + 3) * 16 + bp);
#pragma unroll
                for (int c = 0; c < 12; c++) {
                    const float* wp = s_w1 + c * 1024 + 2 * k;
                    ulonglong2 w01 = *(const ulonglong2*)(wp);
                    ulonglong2 w23 = *(const ulonglong2*)(wp + 4);
                    fma2(acc1[c], a0, w01.x); fma2(acc1[c], a1, w01.y);
                    fma2(acc1[c], a2, w23.x); fma2(acc1[c], a3, w23.y);
                }
            }
#pragma unroll
            for (int c = 0; c < 12; c++) {
                ull o = __shfl_xor_sync(0xffffffffu, acc1[c], 16);
                add2(acc1[c], o);
            }
            if (lane < 16) {
#pragma unroll
                for (int c = 0; c < 12; c++)
                    s_part[(w * 12 + c) * 16 + bp] = acc1[c];
            }
        }
        __syncthreads();
        if (tid < 384) {
            int c = tid >> 5, b = tid & 31;
            float sum = 0.f;
#pragma unroll
            for (int s = 0; s < 16; s++)
                sum += s_partf[(((s * 12 + c) * 16 + (b >> 1)) << 1) | (b & 1)];
            sum += s_b[8 + c];
            float ge = 0.5f * sum * (1.0f + erff(sum * 0.70710678118654752f));
            __stcg(&g_kmidT[(p0 + c) * 32 + b], ge);
        }
        gbar(nb * GCTA); nb++;

        // ==== Phase 2: K = tanh(kmid @ kW2 + kb2)*0.5; direct ldcg ==========
        {
            ull acc2[4] = {0, 0, 0, 0};
            const ull* kp = (const ull*)g_kmidT;
#pragma unroll 4
            for (int kq = 0; kq < 12; kq++) {
                int k = ks2 + 4 * kq;
                ull a0 = __ldcg(kp + (k + 0) * 16 + bp);
                ull a1 = __ldcg(kp + (k + 1) * 16 + bp);
                ull a2 = __ldcg(kp + (k + 2) * 16 + bp);
                ull a3 = __ldcg(kp + (k + 3) * 16 + bp);
#pragma unroll
                for (int c = 0; c < 4; c++) {
                    const float* wp = s_w2 + c * 3072 + 2 * k;
                    ulonglong2 w01 = *(const ulonglong2*)(wp);
                    ulonglong2 w23 = *(const ulonglong2*)(wp + 4);
                    fma2(acc2[c], a0, w01.x); fma2(acc2[c], a1, w01.y);
                    fma2(acc2[c], a2, w23.x); fma2(acc2[c], a3, w23.y);
                }
            }
#pragma unroll
            for (int c = 0; c < 4; c++) {
                ull o = __shfl_xor_sync(0xffffffffu, acc2[c], 16);
                add2(acc2[c], o);
            }
            if (lane < 16) {
#pragma unroll
                for (int c = 0; c < 4; c++)
                    s_part[(w * 4 + c) * 16 + bp] = acc2[c];
            }
        }
        __syncthreads();
        if (tid < 128) {
            float sum = 0.f;
#pragma unroll
            for (int s = 0; s < 16; s++)
                sum += s_partf[(((s * 4 + cI) * 16 + (bI >> 1)) << 1) | (bI & 1)];
            float K  = tanhf(sum + s_b[20 + cI]) * 0.5f;
            float An = s_b[24 + cI] * (1.0f - K * K);
            float cn = An * s_cold[tid] + K * s_inn[tid] + s_M[tid];
            s_A[tid] = An;
            __stcg(&g_cU[(j0 + cI) * 32 + bI], cn);
        }
        gbar(nb * GCTA); nb++;
    }

    // ==== tail: hs[NL-1] = scale * c ========================================
    {
        float ss0 = 0.f, ss1 = 0.f, ss2 = 0.f, ss3 = 0.f;
#pragma unroll
        for (int r = 0; r < 8; r++) {
            int i4 = tid + 512 * r;
            float4 v = __ldcg(((const float4*)g_cU) + i4);
            ss0 += v.x * v.x; ss1 += v.y * v.y;
            ss2 += v.z * v.z; ss3 += v.w * v.w;
        }
#pragma unroll
        for (int off = 16; off >= 8; off >>= 1) {
            ss0 += __shfl_xor_sync(0xffffffffu, ss0, off);
            ss1 += __shfl_xor_sync(0xffffffffu, ss1, off);
            ss2 += __shfl_xor_sync(0xffffffffu, ss2, off);
            ss3 += __shfl_xor_sync(0xffffffffu, ss3, off);
        }
        if (lane < 8)
            ((float4*)s_partf)[w * 8 + lane] = make_float4(ss0, ss1, ss2, ss3);
        __syncthreads();
        if (tid < 32) {
            float sum = 0.f;
#pragma unroll
            for (int ww = 0; ww < 16; ww++) sum += s_partf[ww * 32 + tid];
            s_inn[tid] = fminf(1.0f, 10.0f * rsqrtf(sum + 1e-6f));
        }
        __syncthreads();
        if (tid < 128) {
            float cOwn = __ldcg(&g_cU[(j0 + cI) * 32 + bI]);
            g_hs[((size_t)bI * NL + (NL - 1)) * NH + j0 + cI] = cOwn * s_inn[bI];
        }
    }
}

// ---------------- launch orchestration ---------------------------------------
extern "C" void kernel_launch(void* const* d_in, const int* in_sizes, int n_in,
                              void* d_out, int out_size) {
    const float* x          = (const float*)d_in[0];
    const float* norm_w     = (const float*)d_in[1];
    const float* W_ih       = (const float*)d_in[2];
    const float* b_ih       = (const float*)d_in[3];
    const float* W_hh       = (const float*)d_in[4];
    const float* b_hh       = (const float*)d_in[5];
    const float* log_lambda = (const float*)d_in[6];
    const float* k_W1       = (const float*)d_in[7];
    const float* k_b1       = (const float*)d_in[8];
    const float* k_W2       = (const float*)d_in[9];
    const float* k_b2       = (const float*)d_in[10];
    const float* Wo         = (const float*)d_in[11];
    float* out = (float*)d_out;

    float *p_xn, *p_gx, *p_hs, *p_yb;
    cudaGetSymbolAddress((void**)&p_xn, g_xn);
    cudaGetSymbolAddress((void**)&p_gx, g_gx);
    cudaGetSymbolAddress((void**)&p_hs, g_hs);
    cudaGetSymbolAddress((void**)&p_yb, g_yb);

    cudaFuncSetAttribute(scan_kernel,
                         cudaFuncAttributeMaxDynamicSharedMemorySize,
                         SCAN_SMEM_FLOATS * 4);

    for (int l = 0; l < 2; l++) {
        const float* xin = (l == 0) ? x : p_yb;
        rmsnorm_kernel<<<16384, 128>>>(xin, norm_w, p_xn);
        sgemm_bias<<<dim3(8, 128), 256>>>(p_xn, W_ih + (size_t)l * 512 * 1024,
                                          b_ih + l * 1024, p_gx,
                                          16384, 1024, 512);
        reset_bar_kernel<<<1, 1>>>();
        scan_kernel<<<GCTA, 512, SCAN_SMEM_FLOATS * 4>>>(
            p_gx,
            W_hh + (size_t)l * 512 * 1024, b_hh + l * 1024,
            log_lambda + l * 512,
            k_W1 + (size_t)l * 512 * 1536, k_b1 + l * 1536,
            k_W2 + (size_t)l * 1536 * 512, k_b2 + l * 512);
        sgemm_bias<<<dim3(4, 128), 256>>>(p_hs, Wo + (size_t)l * 512 * 512,
                                          nullptr, (l == 0) ? p_yb : out,
                                          16384, 512, 512);
    }
}